// round 3
// baseline (speedup 1.0000x reference)
#include <cuda_runtime.h>
#include <math.h>

#define BATCH 8
#define NPTS  2048
#define NJ    21
#define NWEIGHTS 778
#define TOTAL (BATCH*NPTS)

// ---------------- device scratch (no allocation allowed) ----------------
__device__ unsigned int g_wbits[NWEIGHTS];
__device__ float4 g_q4[TOTAL];        // gen_pc packed: x,y,z, bitcast(joint mask bits)
__device__ int    g_label[TOTAL];     // argmin segment label per (b,m)
__device__ float4 g_tsorted[TOTAL];   // target_pc sorted by label per batch
__device__ int    g_counts[BATCH*NJ];
__device__ int    g_offs[BATCH*(NJ+1)];
__device__ int    g_cursor[BATCH*NJ];
__device__ float  g_cham1, g_cham2;
__device__ float  g_j1[NJ], g_j2[NJ];

// JOINT_RANGES flattened [j][axis][lo,hi]
__constant__ float c_ranges[NJ*6] = {
  -1.57f,1.57f, -1.57f,1.57f, -1.57f,1.57f,
  -1.05f,1.05f, 0.f,0.f, -0.79f,0.26f,
  -0.52f,0.52f, 0.f,0.f, -0.35f,0.79f,
  -0.26f,0.26f, 0.f,0.f, 0.f,0.f,
  -1.05f,0.f,   0.f,0.f, 0.f,0.f,
   0.f,0.f,     0.f,0.f, 0.f,0.f,
  -1.05f,0.26f, 0.f,0.f, -0.52f,0.26f,
  -0.52f,0.f,   0.f,0.f, 0.f,0.f,
  -0.52f,0.f,   0.f,0.f, 0.f,0.f,
   0.f,0.f,     0.f,0.f, 0.f,0.f,
  -1.05f,0.26f, 0.f,0.f, -0.52f,0.26f,
  -0.52f,0.f,   0.f,0.f, 0.f,0.f,
  -0.52f,0.f,   0.f,0.f, 0.f,0.f,
   0.f,0.f,     0.f,0.f, 0.f,0.f,
  -1.05f,0.26f, 0.f,0.f, -0.52f,0.26f,
  -0.52f,0.f,   0.f,0.f, 0.f,0.f,
  -0.52f,0.f,   0.f,0.f, 0.f,0.f,
   0.f,0.f,     0.f,0.f, 0.f,0.f,
  -1.05f,0.26f, 0.f,0.f, -0.52f,0.26f,
  -0.52f,0.f,   0.f,0.f, 0.f,0.f,
  -0.52f,0.f,   0.f,0.f, 0.f,0.f
};

// ---------------- K0: zero accumulators ----------------
__global__ void k_init() {
    int t = threadIdx.x;
    for (int i = t; i < BATCH*NJ; i += blockDim.x) g_counts[i] = 0;
    if (t < NJ) { g_j1[t] = 0.f; g_j2[t] = 0.f; }
    if (t == 0) { g_cham1 = 0.f; g_cham2 = 0.f; }
}

// ---------------- K1: threshold bone_weights into per-vertex bitmask ----------------
__global__ void k_wbits(const float* __restrict__ bw) {
    int t = blockIdx.x * blockDim.x + threadIdx.x;
    if (t >= NWEIGHTS) return;
    unsigned int bits = 0;
#pragma unroll
    for (int i = 0; i < NJ; i++)
        bits |= (bw[i*NWEIGHTS + t] > 0.15f) ? (1u << i) : 0u;
    g_wbits[t] = bits;
}

// ---------------- K2: pack gen_pc + joint mask bits ----------------
__global__ void k_pack(const float* __restrict__ gen, const int* __restrict__ idxs) {
    int t = blockIdx.x * blockDim.x + threadIdx.x;
    if (t >= TOTAL) return;
    float4 q;
    q.x = gen[3*t];
    q.y = gen[3*t+1];
    q.z = gen[3*t+2];
    q.w = __uint_as_float(g_wbits[idxs[t]]);
    g_q4[t] = q;
}

// ---------------- K3: argmin label per (b,m) + per-batch histogram ----------------
__global__ void k_label(const float* __restrict__ seg) {
    __shared__ int h[NJ];
    int t = threadIdx.x;
    if (t < NJ) h[t] = 0;
    __syncthreads();
    int gid = blockIdx.x * blockDim.x + t;          // 64 blocks x 256 = 16384
    int batch = blockIdx.x >> 3;                    // 8 blocks per batch
    const float* s = seg + (size_t)gid * NJ;
    float best = s[0];
    int bi = 0;
#pragma unroll
    for (int k = 1; k < NJ; k++) {
        float v = s[k];
        if (v < best) { best = v; bi = k; }
    }
    g_label[gid] = bi;
    atomicAdd(&h[bi], 1);
    __syncthreads();
    if (t < NJ) atomicAdd(&g_counts[batch*NJ + t], h[t]);
}

// ---------------- K4: per-batch prefix offsets + cursors ----------------
__global__ void k_offs() {
    int b = threadIdx.x;
    if (b >= BATCH) return;
    int run = 0;
    for (int k = 0; k < NJ; k++) {
        g_offs[b*(NJ+1) + k] = run;
        g_cursor[b*NJ + k] = run;
        run += g_counts[b*NJ + k];
    }
    g_offs[b*(NJ+1) + NJ] = run;
}

// ---------------- K5: scatter target points into label-sorted order ----------------
__global__ void k_scatter(const float* __restrict__ tpc) {
    int t = blockIdx.x * blockDim.x + threadIdx.x;
    if (t >= TOTAL) return;
    int b = t >> 11;
    int lab = g_label[t];
    int pos = atomicAdd(&g_cursor[b*NJ + lab], 1);
    float4 v;
    v.x = tpc[3*t]; v.y = tpc[3*t+1]; v.z = tpc[3*t+2]; v.w = 0.f;
    g_tsorted[(b << 11) + pos] = v;
}

// ---------------- K6: row pass — dist1 + per-joint d1 ----------------
// grid 2048 blocks x 256 threads; warp per (b,n)
__global__ void __launch_bounds__(256) k_row() {
    __shared__ float4 sT[NPTS];      // 32 KB
    __shared__ int    soff[NJ+1];
    __shared__ float  sj[NJ];
    __shared__ float  scham;
    int t = threadIdx.x;
    int b = blockIdx.x >> 8;                 // 256 blocks per batch
    int nbase = (blockIdx.x & 255) * 8;

    for (int i = t; i < NPTS; i += 256) sT[i] = g_tsorted[(b << 11) + i];
    if (t < NJ+1) soff[t] = g_offs[b*(NJ+1) + t];
    if (t < NJ) sj[t] = 0.f;
    if (t == 0) scham = 0.f;
    __syncthreads();

    int warp = t >> 5, lane = t & 31;
    int n = nbase + warp;
    float4 q = g_q4[(b << 11) + n];
    unsigned int bits = __float_as_uint(q.w);
    float gmin = 1e30f;

    for (int grp = 0; grp < NJ; grp++) {
        int s = soff[grp], e = soff[grp+1];
        float lmin = 1e30f;
#pragma unroll 2
        for (int m = s + lane; m < e; m += 32) {
            float4 tp = sT[m];
            float dx = q.x - tp.x, dy = q.y - tp.y, dz = q.z - tp.z;
            float d2 = dx*dx;
            d2 = fmaf(dy, dy, d2);
            d2 = fmaf(dz, dz, d2);
            lmin = fminf(lmin, d2);
        }
        gmin = fminf(gmin, lmin);
#pragma unroll
        for (int o = 16; o > 0; o >>= 1)
            lmin = fminf(lmin, __shfl_xor_sync(0xffffffffu, lmin, o));
        if (lane == 0 && ((bits >> grp) & 1u)) {
            float d = sqrtf(lmin);
            if (d < 10.0f) atomicAdd(&sj[grp], d);
        }
    }
#pragma unroll
    for (int o = 16; o > 0; o >>= 1)
        gmin = fminf(gmin, __shfl_xor_sync(0xffffffffu, gmin, o));
    if (lane == 0) atomicAdd(&scham, sqrtf(gmin));
    __syncthreads();
    if (t < NJ) atomicAdd(&g_j1[t], sj[t]);
    if (t == 0) atomicAdd(&g_cham1, scham);
}

// ---------------- K7: column pass — dist2 + per-joint d2 ----------------
// grid 2048 blocks x 256 threads; warp per (b,m)
__global__ void __launch_bounds__(256) k_col(const float* __restrict__ tpc) {
    __shared__ float4 sQ[NPTS];      // 32 KB
    __shared__ float  sj[NJ];
    __shared__ float  scham;
    int t = threadIdx.x;
    int b = blockIdx.x >> 8;
    int mbase = (blockIdx.x & 255) * 8;

    for (int i = t; i < NPTS; i += 256) sQ[i] = g_q4[(b << 11) + i];
    if (t < NJ) sj[t] = 0.f;
    if (t == 0) scham = 0.f;
    __syncthreads();

    int warp = t >> 5, lane = t & 31;
    int m = mbase + warp;
    int gi = (b << 11) + m;
    float tx = tpc[3*gi], ty = tpc[3*gi+1], tz = tpc[3*gi+2];
    int p = g_label[gi];
    float gmin = 1e30f, pmin = 1e30f;

#pragma unroll 4
    for (int n = lane; n < NPTS; n += 32) {
        float4 qn = sQ[n];
        float dx = tx - qn.x, dy = ty - qn.y, dz = tz - qn.z;
        float d2 = dx*dx;
        d2 = fmaf(dy, dy, d2);
        d2 = fmaf(dz, dz, d2);
        gmin = fminf(gmin, d2);
        unsigned int bb = __float_as_uint(qn.w);
        if ((bb >> p) & 1u) pmin = fminf(pmin, d2);
    }
#pragma unroll
    for (int o = 16; o > 0; o >>= 1) {
        gmin = fminf(gmin, __shfl_xor_sync(0xffffffffu, gmin, o));
        pmin = fminf(pmin, __shfl_xor_sync(0xffffffffu, pmin, o));
    }
    if (lane == 0) {
        atomicAdd(&scham, sqrtf(gmin));
        float d = sqrtf(pmin);
        if (d < 10.0f) atomicAdd(&sj[p], d);
    }
    __syncthreads();
    if (t < NJ) atomicAdd(&g_j2[t], sj[t]);
    if (t == 0) atomicAdd(&g_cham2, scham);
}

// ---------------- K8: finalize — coord MSE, physical loss, combine ----------------
__global__ void k_final(const float* __restrict__ cp, const float* __restrict__ qt,
                        const float* __restrict__ tc, float* __restrict__ out) {
    __shared__ float s_coord, s_p;
    int t = threadIdx.x;
    if (t == 0) { s_coord = 0.f; s_p = 0.f; }
    __syncthreads();

    float ca = 0.f;
    for (int i = t; i < BATCH*NJ*3; i += blockDim.x) {
        float d = cp[i] - tc[i];
        ca += d * d;
    }
    float pa = 0.f;
    for (int i = t; i < BATCH*NJ; i += blockDim.x) {
        int j = i % NJ;
        float w = qt[4*i], x = qt[4*i+1], y = qt[4*i+2], z = qt[4*i+3];
        float inv = 1.0f / sqrtf(w*w + x*x + y*y + z*z);
        w *= inv; x *= inv; y *= inv; z *= inv;
        float ang[3];
        ang[0] = atan2f(2.f*(w*x + y*z), 1.f - 2.f*(x*x + y*y));
        ang[1] = asinf(fminf(fmaxf(2.f*(w*y - z*x), -1.f), 1.f));
        ang[2] = atan2f(2.f*(w*z + x*y), 1.f - 2.f*(y*y + z*z));
#pragma unroll
        for (int c = 0; c < 3; c++) {
            float lo = c_ranges[j*6 + c*2], hi = c_ranges[j*6 + c*2 + 1];
            pa += fmaxf(lo - ang[c], 0.f) + fmaxf(ang[c] - hi, 0.f);
        }
    }
    atomicAdd(&s_coord, ca);
    atomicAdd(&s_p, pa);
    __syncthreads();
    if (t == 0) {
        float coord = s_coord / (float)(BATCH*NJ*3);
        float pl    = s_p / (float)(BATCH*NJ);
        float cham  = (g_cham1 + g_cham2) / (float)TOTAL;
        float jm = 0.f;
        for (int i = 0; i < NJ; i++) {
            float jl = (g_j1[i] + g_j2[i]) / (float)TOTAL;
            out[2 + i] = jl;
            jm += jl;
        }
        jm /= (float)NJ;
        out[0]  = 0.1f*cham + 0.1f*jm + coord + 0.1f*pl;
        out[1]  = coord;
        out[23] = cham;
        out[24] = pl;
    }
}

// ---------------- launch ----------------
extern "C" void kernel_launch(void* const* d_in, const int* in_sizes, int n_in,
                              void* d_out, int out_size) {
    const float* gen_pc      = (const float*)d_in[0];
    const int*   out_idxs    = (const int*)  d_in[1];
    const float* coords_pred = (const float*)d_in[2];
    const float* quats       = (const float*)d_in[3];
    const float* seg_logits  = (const float*)d_in[4];
    const float* bone_w      = (const float*)d_in[5];
    const float* tcoords     = (const float*)d_in[6];
    const float* target_pc   = (const float*)d_in[7];
    float* out = (float*)d_out;

    k_init   <<<1, 256>>>();
    k_wbits  <<<(NWEIGHTS + 255)/256, 256>>>(bone_w);
    k_pack   <<<TOTAL/256, 256>>>(gen_pc, out_idxs);
    k_label  <<<TOTAL/256, 256>>>(seg_logits);
    k_offs   <<<1, 32>>>();
    k_scatter<<<TOTAL/256, 256>>>(target_pc);
    k_row    <<<2048, 256>>>();
    k_col    <<<2048, 256>>>(target_pc);
    k_final  <<<1, 256>>>(coords_pred, quats, tcoords, out);
}

// round 4
// speedup vs baseline: 1.2289x; 1.2289x over previous
#include <cuda_runtime.h>
#include <math.h>

#define BATCH 8
#define NPTS  2048
#define NJ    21
#define NWGT  778
#define TOTAL (BATCH*NPTS)

// ---------------- device scratch ----------------
__device__ unsigned int g_wbits[NWGT];
__device__ float4 g_q4[TOTAL];          // gen: x,y,z,|q|^2
__device__ unsigned int g_qbits[TOTAL]; // gen joint-mask bits
__device__ int    g_label[TOTAL];       // argmin segment label per (b,m)
__device__ float4 g_tsorted[TOTAL];     // target sorted by label: x,y,z,|t|^2
__device__ int    g_counts[BATCH*NJ];
__device__ int    g_offs[BATCH*(NJ+1)];
__device__ int    g_cursor[BATCH*NJ];
__device__ float  g_cham1, g_cham2;
__device__ float  g_j1[NJ], g_j2[NJ];

__constant__ float c_ranges[NJ*6] = {
  -1.57f,1.57f, -1.57f,1.57f, -1.57f,1.57f,
  -1.05f,1.05f, 0.f,0.f, -0.79f,0.26f,
  -0.52f,0.52f, 0.f,0.f, -0.35f,0.79f,
  -0.26f,0.26f, 0.f,0.f, 0.f,0.f,
  -1.05f,0.f,   0.f,0.f, 0.f,0.f,
   0.f,0.f,     0.f,0.f, 0.f,0.f,
  -1.05f,0.26f, 0.f,0.f, -0.52f,0.26f,
  -0.52f,0.f,   0.f,0.f, 0.f,0.f,
  -0.52f,0.f,   0.f,0.f, 0.f,0.f,
   0.f,0.f,     0.f,0.f, 0.f,0.f,
  -1.05f,0.26f, 0.f,0.f, -0.52f,0.26f,
  -0.52f,0.f,   0.f,0.f, 0.f,0.f,
  -0.52f,0.f,   0.f,0.f, 0.f,0.f,
   0.f,0.f,     0.f,0.f, 0.f,0.f,
  -1.05f,0.26f, 0.f,0.f, -0.52f,0.26f,
  -0.52f,0.f,   0.f,0.f, 0.f,0.f,
  -0.52f,0.f,   0.f,0.f, 0.f,0.f,
   0.f,0.f,     0.f,0.f, 0.f,0.f,
  -1.05f,0.26f, 0.f,0.f, -0.52f,0.26f,
  -0.52f,0.f,   0.f,0.f, 0.f,0.f,
  -0.52f,0.f,   0.f,0.f, 0.f,0.f
};

// ---- K_A: init accumulators + threshold bone weights into bitmasks ----
__global__ void k_prep(const float* __restrict__ bw) {
    int t = threadIdx.x;
    if (t < BATCH*NJ) g_counts[t] = 0;
    if (t < NJ) { g_j1[t] = 0.f; g_j2[t] = 0.f; }
    if (t == 0) { g_cham1 = 0.f; g_cham2 = 0.f; }
    if (t < NWGT) {
        unsigned int bits = 0;
#pragma unroll
        for (int i = 0; i < NJ; i++)
            bits |= (bw[i*NWGT + t] > 0.15f) ? (1u << i) : 0u;
        g_wbits[t] = bits;
    }
}

// ---- K_B: pack gen (norms + bits) AND compute labels (coalesced) + histogram ----
__global__ void __launch_bounds__(256) k_pack_label(
        const float* __restrict__ gen, const int* __restrict__ idxs,
        const float* __restrict__ seg) {
    __shared__ float sl[256*NJ];
    __shared__ int h[NJ];
    int t = threadIdx.x, blk = blockIdx.x;
    int gid = blk*256 + t;
    if (t < NJ) h[t] = 0;
    // coalesced stage of 256 points' logits
    const float* segb = seg + (size_t)blk*256*NJ;
    for (int i = t; i < 256*NJ; i += 256) sl[i] = segb[i];
    // pack gen point
    float x = gen[3*gid], y = gen[3*gid+1], z = gen[3*gid+2];
    float4 q; q.x = x; q.y = y; q.z = z; q.w = x*x + y*y + z*z;
    g_q4[gid] = q;
    g_qbits[gid] = g_wbits[idxs[gid]];
    __syncthreads();
    const float* s = &sl[t*NJ];
    float best = s[0]; int bi = 0;
#pragma unroll
    for (int k = 1; k < NJ; k++) {
        float v = s[k];
        if (v < best) { best = v; bi = k; }
    }
    g_label[gid] = bi;
    atomicAdd(&h[bi], 1);
    __syncthreads();
    if (t < NJ) atomicAdd(&g_counts[(blk >> 3)*NJ + t], h[t]);
}

// ---- K_C: per-batch prefix ----
__global__ void k_offs() {
    int b = threadIdx.x;
    if (b >= BATCH) return;
    int run = 0;
    for (int k = 0; k < NJ; k++) {
        g_offs[b*(NJ+1) + k] = run;
        g_cursor[b*NJ + k] = run;
        run += g_counts[b*NJ + k];
    }
    g_offs[b*(NJ+1) + NJ] = run;
}

// ---- K_D: scatter targets into label-sorted order, with |t|^2 ----
__global__ void k_scatter(const float* __restrict__ tpc) {
    int gid = blockIdx.x * blockDim.x + threadIdx.x;
    if (gid >= TOTAL) return;
    int b = gid >> 11;
    int lab = g_label[gid];
    int pos = atomicAdd(&g_cursor[b*NJ + lab], 1);
    float x = tpc[3*gid], y = tpc[3*gid+1], z = tpc[3*gid+2];
    float4 v; v.x = x; v.y = y; v.z = z; v.w = x*x + y*y + z*z;
    g_tsorted[(b << 11) + pos] = v;
}

// ---- K_E: row pass. Lane-owns-query, broadcast scan of sorted targets.
// 16 queries per warp, two half-warps scan complementary halves of each group.
__global__ void __launch_bounds__(128) k_row() {
    __shared__ float4 sT[NPTS];      // 32 KB
    __shared__ int    soff[NJ+1];
    __shared__ float  sj[NJ];
    __shared__ float  scham;
    int t = threadIdx.x;
    int b = blockIdx.x >> 5;         // 32 blocks per batch
    int qblk = blockIdx.x & 31;

    for (int i = t; i < NPTS; i += 128) sT[i] = g_tsorted[(b << 11) + i];
    if (t < NJ+1) soff[t] = g_offs[b*(NJ+1) + t];
    if (t < NJ) sj[t] = 0.f;
    if (t == 0) scham = 0.f;
    __syncthreads();

    int warp = t >> 5, lane = t & 31, half = lane >> 4;
    int qi = qblk*64 + warp*16 + (lane & 15);
    float4 q = g_q4[(b << 11) + qi];
    unsigned int bits = g_qbits[(b << 11) + qi];
    float qn2 = q.w;
    float gmall = 1e30f;

    for (int grp = 0; grp < NJ; grp++) {
        int s = soff[grp], e = soff[grp+1];
        int len = e - s;
        if (len > 0) {
            int hlen = (len + 1) >> 1;
            int m0 = s + half*hlen;
            float gm = 1e30f;
#pragma unroll 4
            for (int i = 0; i < hlen; i++) {
                int m = m0 + i;
                m = (m < e) ? m : (e - 1);     // duplicate last: harmless for min
                float4 tp = sT[m];
                float dot = q.x*tp.x;
                dot = fmaf(q.y, tp.y, dot);
                dot = fmaf(q.z, tp.z, dot);
                float val = fmaf(-2.f, dot, tp.w);   // |t|^2 - 2 q.t
                gm = fminf(gm, val);
            }
            gm = fminf(gm, __shfl_xor_sync(0xffffffffu, gm, 16));
            gmall = fminf(gmall, gm);
            float d = sqrtf(fmaxf(gm + qn2, 0.f));
            float c = (((bits >> grp) & 1u) && d < 10.f) ? d : 0.f;
            c += __shfl_xor_sync(0xffffffffu, c, 1);
            c += __shfl_xor_sync(0xffffffffu, c, 2);
            c += __shfl_xor_sync(0xffffffffu, c, 4);
            c += __shfl_xor_sync(0xffffffffu, c, 8);
            if (lane == 0) atomicAdd(&sj[grp], c);
        }
    }
    float d1 = sqrtf(fmaxf(gmall + qn2, 0.f));
    d1 += __shfl_xor_sync(0xffffffffu, d1, 1);
    d1 += __shfl_xor_sync(0xffffffffu, d1, 2);
    d1 += __shfl_xor_sync(0xffffffffu, d1, 4);
    d1 += __shfl_xor_sync(0xffffffffu, d1, 8);
    if (lane == 0) atomicAdd(&scham, d1);
    __syncthreads();
    if (t < NJ) atomicAdd(&g_j1[t], sj[t]);
    if (t == 0) atomicAdd(&g_cham1, scham);
}

// ---- K_F: column pass. Lane-owns-target, broadcast scan of gen points. ----
__global__ void __launch_bounds__(128) k_col(const float* __restrict__ tpc) {
    __shared__ float4 sQ[NPTS];              // 32 KB
    __shared__ unsigned int sB[NPTS];        // 8 KB
    __shared__ float sj[NJ];
    __shared__ float scham;
    int t = threadIdx.x;
    int b = blockIdx.x >> 5;
    int mblk = blockIdx.x & 31;

    for (int i = t; i < NPTS; i += 128) {
        sQ[i] = g_q4[(b << 11) + i];
        sB[i] = g_qbits[(b << 11) + i];
    }
    if (t < NJ) sj[t] = 0.f;
    if (t == 0) scham = 0.f;
    __syncthreads();

    int warp = t >> 5, lane = t & 31, half = lane >> 4;
    int mi = mblk*64 + warp*16 + (lane & 15);
    int gi = (b << 11) + mi;
    float tx = tpc[3*gi], ty = tpc[3*gi+1], tz = tpc[3*gi+2];
    float tn2 = tx*tx + ty*ty + tz*tz;
    int p = g_label[gi];
    unsigned int mymask = 1u << p;
    float gmin = 1e30f, pmin = 1e30f;
    int n0 = half * (NPTS/2);

#pragma unroll 4
    for (int i = 0; i < NPTS/2; i++) {
        int n = n0 + i;
        float4 qn = sQ[n];
        unsigned int bb = sB[n];
        float dot = tx*qn.x;
        dot = fmaf(ty, qn.y, dot);
        dot = fmaf(tz, qn.z, dot);
        float val = fmaf(-2.f, dot, qn.w);   // |q|^2 - 2 t.q
        gmin = fminf(gmin, val);
        if (bb & mymask) pmin = fminf(pmin, val);
    }
    gmin = fminf(gmin, __shfl_xor_sync(0xffffffffu, gmin, 16));
    pmin = fminf(pmin, __shfl_xor_sync(0xffffffffu, pmin, 16));
    float d = sqrtf(fmaxf(gmin + tn2, 0.f));
    float dj = sqrtf(fmaxf(pmin + tn2, 0.f));
    d += __shfl_xor_sync(0xffffffffu, d, 1);
    d += __shfl_xor_sync(0xffffffffu, d, 2);
    d += __shfl_xor_sync(0xffffffffu, d, 4);
    d += __shfl_xor_sync(0xffffffffu, d, 8);
    if (lane == 0) atomicAdd(&scham, d);
    if (half == 0 && dj < 10.f) atomicAdd(&sj[p], dj);
    __syncthreads();
    if (t < NJ) atomicAdd(&g_j2[t], sj[t]);
    if (t == 0) atomicAdd(&g_cham2, scham);
}

// ---- K_G: finalize ----
__global__ void k_final(const float* __restrict__ cp, const float* __restrict__ qt,
                        const float* __restrict__ tc, float* __restrict__ out) {
    __shared__ float s_coord, s_p;
    int t = threadIdx.x;
    if (t == 0) { s_coord = 0.f; s_p = 0.f; }
    __syncthreads();

    float ca = 0.f;
    for (int i = t; i < BATCH*NJ*3; i += blockDim.x) {
        float d = cp[i] - tc[i];
        ca += d * d;
    }
    float pa = 0.f;
    for (int i = t; i < BATCH*NJ; i += blockDim.x) {
        int j = i % NJ;
        float w = qt[4*i], x = qt[4*i+1], y = qt[4*i+2], z = qt[4*i+3];
        float inv = 1.0f / sqrtf(w*w + x*x + y*y + z*z);
        w *= inv; x *= inv; y *= inv; z *= inv;
        float ang0 = atan2f(2.f*(w*x + y*z), 1.f - 2.f*(x*x + y*y));
        float ang1 = asinf(fminf(fmaxf(2.f*(w*y - z*x), -1.f), 1.f));
        float ang2 = atan2f(2.f*(w*z + x*y), 1.f - 2.f*(y*y + z*z));
        float a[3] = {ang0, ang1, ang2};
#pragma unroll
        for (int c = 0; c < 3; c++) {
            float lo = c_ranges[j*6 + c*2], hi = c_ranges[j*6 + c*2 + 1];
            pa += fmaxf(lo - a[c], 0.f) + fmaxf(a[c] - hi, 0.f);
        }
    }
    atomicAdd(&s_coord, ca);
    atomicAdd(&s_p, pa);
    __syncthreads();
    if (t == 0) {
        float coord = s_coord / (float)(BATCH*NJ*3);
        float pl    = s_p / (float)(BATCH*NJ);
        float cham  = (g_cham1 + g_cham2) / (float)TOTAL;
        float jm = 0.f;
        for (int i = 0; i < NJ; i++) {
            float jl = (g_j1[i] + g_j2[i]) / (float)TOTAL;
            out[2 + i] = jl;
            jm += jl;
        }
        jm /= (float)NJ;
        out[0]  = 0.1f*cham + 0.1f*jm + coord + 0.1f*pl;
        out[1]  = coord;
        out[23] = cham;
        out[24] = pl;
    }
}

// ---------------- launch ----------------
extern "C" void kernel_launch(void* const* d_in, const int* in_sizes, int n_in,
                              void* d_out, int out_size) {
    const float* gen_pc      = (const float*)d_in[0];
    const int*   out_idxs    = (const int*)  d_in[1];
    const float* coords_pred = (const float*)d_in[2];
    const float* quats       = (const float*)d_in[3];
    const float* seg_logits  = (const float*)d_in[4];
    const float* bone_w      = (const float*)d_in[5];
    const float* tcoords     = (const float*)d_in[6];
    const float* target_pc   = (const float*)d_in[7];
    float* out = (float*)d_out;

    k_prep       <<<1, 1024>>>(bone_w);
    k_pack_label <<<TOTAL/256, 256>>>(gen_pc, out_idxs, seg_logits);
    k_offs       <<<1, 32>>>();
    k_scatter    <<<TOTAL/256, 256>>>(target_pc);
    k_row        <<<256, 128>>>();
    k_col        <<<256, 128>>>(target_pc);
    k_final      <<<1, 256>>>(coords_pred, quats, tcoords, out);
}